// round 13
// baseline (speedup 1.0000x reference)
#include <cuda_runtime.h>
#include <cuda_fp16.h>
#include <cstdint>

#define NMAX 100000
#define EMAX 1000000
#define LMAX 200000

// ---------------------------------------------------------------------------
// Static device scratch (allocation-free)
// ---------------------------------------------------------------------------
__device__ int     g_deg[NMAX];
__device__ float   g_dinv[NMAX];
__device__ int     g_off[NMAX];              // block-local exclusive scan
__device__ int     g_cur[NMAX];              // fill cursors
__device__ int     g_bsum[256];              // scan block sums (exclusive)
__device__ int     g_ticket;                 // scan last-block ticket
__device__ int     g_csr[EMAX];              // CSR: src node per slot
__device__ uint4   g_h[(size_t)NMAX * 16];   // h = x@W, fp16 (256 B/row)
__device__ uint2   g_x2[(size_t)NMAX * 32];  // layer output, fp16 (both layers)
__device__ __half  g_wh[2 * 128 * 128];      // W1,W2 pre-converted to fp16
__device__ int     g_eidx[2 * EMAX];
__device__ int     g_lidx[2 * LMAX];
__device__ int     g_is64;

// ---------------------------------------------------------------------------
// PTX helpers
// ---------------------------------------------------------------------------
__device__ __forceinline__ uint32_t smem_u32(const void* p) {
    uint32_t a;
    asm("{ .reg .u64 t; cvta.to.shared.u64 t, %1; cvt.u32.u64 %0, t; }"
        : "=r"(a) : "l"(p));
    return a;
}
__device__ __forceinline__ void cp16(uint32_t dst, const void* src) {
    asm volatile("cp.async.cg.shared.global [%0], [%1], 16;"
                 :: "r"(dst), "l"(src) : "memory");
}
__device__ __forceinline__ void cp16z(uint32_t dst, const void* src, int sz) {
    asm volatile("cp.async.cg.shared.global [%0], [%1], 16, %2;"
                 :: "r"(dst), "l"(src), "r"(sz) : "memory");
}
#define CP_COMMIT() asm volatile("cp.async.commit_group;" ::: "memory")
#define CP_WAIT0()  asm volatile("cp.async.wait_group 0;" ::: "memory")
#define LDSM_X4(r0, r1, r2, r3, addr)                                        \
    asm volatile("ldmatrix.sync.aligned.m8n8.x4.shared.b16 {%0,%1,%2,%3}, [%4];" \
                 : "=r"(r0), "=r"(r1), "=r"(r2), "=r"(r3) : "r"(addr))
#define LDSM_X4T(r0, r1, r2, r3, addr)                                       \
    asm volatile("ldmatrix.sync.aligned.m8n8.x4.trans.shared.b16 {%0,%1,%2,%3}, [%4];" \
                 : "=r"(r0), "=r"(r1), "=r"(r2), "=r"(r3) : "r"(addr))
#define MMA_16816(c0, c1, c2, c3, a0, a1, a2, a3, b0, b1)                    \
    asm volatile("mma.sync.aligned.m16n8k16.row.col.f32.f16.f16.f32 "        \
                 "{%0,%1,%2,%3}, {%4,%5,%6,%7}, {%8,%9}, {%0,%1,%2,%3};"     \
                 : "+f"(c0), "+f"(c1), "+f"(c2), "+f"(c3)                    \
                 : "r"(a0), "r"(a1), "r"(a2), "r"(a3), "r"(b0), "r"(b1))

// ---------------------------------------------------------------------------
// init: dtype sniff + zero deg/cur + reset scan ticket
// ---------------------------------------------------------------------------
__global__ void k_init(const unsigned* __restrict__ w, int n) {
    int i = blockIdx.x * blockDim.x + threadIdx.x;
    if (i == 0) {
        int is64 = 1;
        for (int j = 0; j < 32; j++)
            if (w[2 * j + 1] != 0u) { is64 = 0; break; }
        g_is64 = is64;
        g_ticket = 0;
    }
    if (i < n) { g_deg[i] = 0; g_cur[i] = 0; }
}

// merged edge + label decode (one index space); edges also histogram degrees
__global__ void k_cvt(const void* __restrict__ eraw, const void* __restrict__ lraw,
                      int E, int L, int n) {
    int i = blockIdx.x * blockDim.x + threadIdx.x;
    int twoE = 2 * E;
    int is64 = g_is64;
    if (i < twoE) {
        long long v = is64 ? ((const long long*)eraw)[i]
                           : (long long)((const int*)eraw)[i];
        int x = (int)v;
        x = x < 0 ? 0 : (x >= n ? n - 1 : x);
        g_eidx[i] = x;
        if (i >= E) atomicAdd(&g_deg[x], 1);
    } else if (i < twoE + 2 * L) {
        int j = i - twoE;
        long long v = is64 ? ((const long long*)lraw)[j]
                           : (long long)((const int*)lraw)[j];
        int x = (int)v;
        x = x < 0 ? 0 : (x >= n ? n - 1 : x);
        g_lidx[j] = x;
    }
}

// W1,W2 -> fp16 (once per call). 8192 float4 slots total.
__global__ void k_wcvt(const float* __restrict__ W1, const float* __restrict__ W2) {
    int i = blockIdx.x * blockDim.x + threadIdx.x;   // 0..8191
    if (i >= 8192) return;
    const float* W = (i < 4096) ? W1 : W2;
    int q = (i < 4096) ? i : i - 4096;
    float4 w4 = *(const float4*)(W + q * 4);
    __half2 p0 = __floats2half2_rn(w4.x, w4.y);
    __half2 p1 = __floats2half2_rn(w4.z, w4.w);
    uint2 pk = { *(uint32_t*)&p0, *(uint32_t*)&p1 };
    *(uint2*)&g_wh[(size_t)i * 4] = pk;
}

// ---------------------------------------------------------------------------
// Tensor-core GEMM (legacy HMMA path):
// g_h[row] = fp16( X[row] @ W );  fp16 inputs, fp32 accumulate.
// use_internal=0: A = Xext (fp32, converted);  =1: A = g_x2 (fp16, cp.async).
// W always from g_wh (fp16, cp.async).
// 256 threads = 8 warps (4M x 2N); warp tile 32M x 64N; K=128 in 8 k16 steps.
// ---------------------------------------------------------------------------
#define HP 136
#define GEMM_SMEM (2 * 128 * HP * 2)   // A + W fp16: 69632 B

__global__ void __launch_bounds__(256, 2)
k_gemm(const float* __restrict__ Xext, int widx, int n, int use_internal) {
    extern __shared__ __half hsm[];
    __half* Asm = hsm;             // [128][HP]
    __half* Wsm = hsm + 128 * HP;  // [128][HP]

    int tid = threadIdx.x;
    int lane = tid & 31;
    int wid = tid >> 5;
    int warpM = wid & 3;
    int warpN = wid >> 2;
    int rowBase = blockIdx.x * 128;

    uint32_t sbA = smem_u32(Asm);
    uint32_t sbW = smem_u32(Wsm);
    const __half* Wh = g_wh + (size_t)widx * 16384;

    // ---- W: fp16 copy via cp.async (16 chunks of 16B per row) ----
#pragma unroll
    for (int i = 0; i < 8; i++) {
        int idx = tid + i * 256;          // 0..2047 16B chunks
        int r = idx >> 4;
        int q = idx & 15;
        cp16(sbW + (uint32_t)(r * HP + q * 8) * 2, Wh + r * 128 + q * 8);
    }
    // ---- A: fp32-convert (LDG+cvt) or fp16 cp.async ----
    if (!use_internal) {
#pragma unroll
        for (int i = 0; i < 16; i++) {
            int idx = tid + i * 256;
            int r = idx >> 5;
            int q = idx & 31;
            int row = rowBase + r;
            float4 a4 = make_float4(0.f, 0.f, 0.f, 0.f);
            if (row < n) a4 = *(const float4*)(Xext + (size_t)row * 128 + q * 4);
            __half2 q0 = __floats2half2_rn(a4.x, a4.y);
            __half2 q1 = __floats2half2_rn(a4.z, a4.w);
            uint2 ak = { *(uint32_t*)&q0, *(uint32_t*)&q1 };
            *(uint2*)&Asm[r * HP + q * 4] = ak;
        }
    } else {
        const __half* Xh = (const __half*)g_x2;   // 128 halves per row
#pragma unroll
        for (int i = 0; i < 8; i++) {
            int idx = tid + i * 256;      // 0..2047 16B chunks
            int r = idx >> 4;
            int q = idx & 15;
            int row = rowBase + r;
            int sz = (row < n) ? 16 : 0;
            cp16z(sbA + (uint32_t)(r * HP + q * 8) * 2,
                  Xh + (size_t)row * 128 + q * 8, sz);
        }
    }
    CP_COMMIT();
    CP_WAIT0();
    __syncthreads();

    float acc[2][8][4];
#pragma unroll
    for (int mt = 0; mt < 2; mt++)
#pragma unroll
        for (int nt = 0; nt < 8; nt++)
#pragma unroll
            for (int r = 0; r < 4; r++) acc[mt][nt][r] = 0.f;

    int aRowL = warpM * 32 + (lane & 15);
    int aColL = 8 * (lane >> 4);
    int bRowL = (lane & 7) + 8 * ((lane >> 3) & 1);
    int bColL = warpN * 64 + 8 * (lane >> 4);

#pragma unroll
    for (int ks = 0; ks < 8; ks++) {
        int kb = ks * 16;
        uint32_t a[2][4];
#pragma unroll
        for (int mt = 0; mt < 2; mt++) {
            uint32_t addr = sbA + (uint32_t)((aRowL + mt * 16) * HP + kb + aColL) * 2;
            LDSM_X4(a[mt][0], a[mt][1], a[mt][2], a[mt][3], addr);
        }
        uint32_t b[8][2];
#pragma unroll
        for (int nt2 = 0; nt2 < 4; nt2++) {
            uint32_t addr = sbW + (uint32_t)((kb + bRowL) * HP + bColL + nt2 * 16) * 2;
            uint32_t r0, r1, r2, r3;
            LDSM_X4T(r0, r1, r2, r3, addr);
            b[nt2 * 2 + 0][0] = r0; b[nt2 * 2 + 0][1] = r1;
            b[nt2 * 2 + 1][0] = r2; b[nt2 * 2 + 1][1] = r3;
        }
#pragma unroll
        for (int mt = 0; mt < 2; mt++)
#pragma unroll
            for (int nt = 0; nt < 8; nt++)
                MMA_16816(acc[mt][nt][0], acc[mt][nt][1],
                          acc[mt][nt][2], acc[mt][nt][3],
                          a[mt][0], a[mt][1], a[mt][2], a[mt][3],
                          b[nt][0], b[nt][1]);
    }

    uint32_t* hOut = (uint32_t*)g_h;   // 64 half2 per row
#pragma unroll
    for (int mt = 0; mt < 2; mt++) {
        int r0 = rowBase + warpM * 32 + mt * 16 + (lane >> 2);
#pragma unroll
        for (int nt = 0; nt < 8; nt++) {
            int colIdx = warpN * 32 + nt * 4 + (lane & 3);
            if (r0 < n) {
                __half2 h = __floats2half2_rn(acc[mt][nt][0], acc[mt][nt][1]);
                hOut[(size_t)r0 * 64 + colIdx] = *(uint32_t*)&h;
            }
            if (r0 + 8 < n) {
                __half2 h = __floats2half2_rn(acc[mt][nt][2], acc[mt][nt][3]);
                hOut[(size_t)(r0 + 8) * 64 + colIdx] = *(uint32_t*)&h;
            }
        }
    }
}

// ---------------------------------------------------------------------------
// scan: block-local exclusive + dinv; last block scans the block sums
// ---------------------------------------------------------------------------
__global__ void k_scan1(int n, int nb) {
    __shared__ int s[512];
    __shared__ int isLast;
    int t = threadIdx.x;
    int i = blockIdx.x * 512 + t;
    int v = (i < n) ? g_deg[i] : 0;
    if (i < n) g_dinv[i] = rsqrtf((float)v + 1.0f);
    s[t] = v;
    __syncthreads();
    for (int off = 1; off < 512; off <<= 1) {
        int add = (t >= off) ? s[t - off] : 0;
        __syncthreads();
        s[t] += add;
        __syncthreads();
    }
    if (i < n) g_off[i] = s[t] - v;
    if (t == 511) g_bsum[blockIdx.x] = s[511];

    __threadfence();
    if (t == 0) isLast = (atomicAdd(&g_ticket, 1) == gridDim.x - 1);
    __syncthreads();
    if (isLast) {
        __threadfence();
        int v2 = (t < nb) ? g_bsum[t] : 0;
        s[t] = (t < 256) ? v2 : 0;
        __syncthreads();
        for (int off = 1; off < 256; off <<= 1) {
            int add = (t < 256 && t >= off) ? s[t - off] : 0;
            __syncthreads();
            if (t < 256) s[t] += add;
            __syncthreads();
        }
        if (t < nb) g_bsum[t] = s[t] - v2;
    }
}

__global__ void k_fill(int E) {
    int i = blockIdx.x * blockDim.x + threadIdx.x;
    if (i >= E) return;
    int s = g_eidx[i];
    int d = g_eidx[E + i];
    int pos = g_off[d] + g_bsum[d >> 9] + atomicAdd(&g_cur[d], 1);
    g_csr[pos] = s;
}

// ---------------------------------------------------------------------------
// CSR pull aggregation + fused finalize (fp16 h gathers, fp32 accumulate):
// x2[d] = fp16( act( dinv[d]*(dinv[d]*h[d] + sum_s dinv[s]*h[s]) + b ) )
// ---------------------------------------------------------------------------
__device__ __forceinline__ void h_load4(int row, int lane, float4& f) {
    uint2 raw = ((const uint2*)g_h)[(size_t)row * 32 + lane];
    __half2 p0 = *(__half2*)&raw.x;
    __half2 p1 = *(__half2*)&raw.y;
    float2 a = __half22float2(p0);
    float2 b = __half22float2(p1);
    f.x = a.x; f.y = a.y; f.z = b.x; f.w = b.y;
}

__global__ void k_agg(const float* __restrict__ bias, int n, int do_relu) {
    int gw = (blockIdx.x * blockDim.x + threadIdx.x) >> 5;
    int lane = threadIdx.x & 31;
    if (gw >= n) return;
    int d = gw;

    float wd = g_dinv[d];
    float4 hd; h_load4(d, lane, hd);
    float4 acc = make_float4(wd * hd.x, wd * hd.y, wd * hd.z, wd * hd.w);

    int o = g_off[d] + g_bsum[d >> 9];
    int c = g_deg[d];

    int j = 0;
    for (; j + 4 <= c; j += 4) {
        int s0 = g_csr[o + j + 0];
        int s1 = g_csr[o + j + 1];
        int s2 = g_csr[o + j + 2];
        int s3 = g_csr[o + j + 3];
        float w0 = g_dinv[s0], w1 = g_dinv[s1], w2 = g_dinv[s2], w3 = g_dinv[s3];
        float4 v0, v1, v2, v3;
        h_load4(s0, lane, v0);
        h_load4(s1, lane, v1);
        h_load4(s2, lane, v2);
        h_load4(s3, lane, v3);
        acc.x = fmaf(w0, v0.x, fmaf(w1, v1.x, fmaf(w2, v2.x, fmaf(w3, v3.x, acc.x))));
        acc.y = fmaf(w0, v0.y, fmaf(w1, v1.y, fmaf(w2, v2.y, fmaf(w3, v3.y, acc.y))));
        acc.z = fmaf(w0, v0.z, fmaf(w1, v1.z, fmaf(w2, v2.z, fmaf(w3, v3.z, acc.z))));
        acc.w = fmaf(w0, v0.w, fmaf(w1, v1.w, fmaf(w2, v2.w, fmaf(w3, v3.w, acc.w))));
    }
    for (; j < c; j++) {
        int s = g_csr[o + j];
        float ws = g_dinv[s];
        float4 v; h_load4(s, lane, v);
        acc.x = fmaf(ws, v.x, acc.x);
        acc.y = fmaf(ws, v.y, acc.y);
        acc.z = fmaf(ws, v.z, acc.z);
        acc.w = fmaf(ws, v.w, acc.w);
    }

    float4 bv = ((const float4*)bias)[lane];
    float4 r = make_float4(fmaf(wd, acc.x, bv.x), fmaf(wd, acc.y, bv.y),
                           fmaf(wd, acc.z, bv.z), fmaf(wd, acc.w, bv.w));
    if (do_relu) {
        r.x = fmaxf(r.x, 0.f); r.y = fmaxf(r.y, 0.f);
        r.z = fmaxf(r.z, 0.f); r.w = fmaxf(r.w, 0.f);
    }
    __half2 h0 = __floats2half2_rn(r.x, r.y);
    __half2 h1 = __floats2half2_rn(r.z, r.w);
    uint2 o2;
    o2.x = *(uint32_t*)&h0;
    o2.y = *(uint32_t*)&h1;
    g_x2[(size_t)d * 32 + lane] = o2;
}

// ---------------------------------------------------------------------------
// edge scoring: one warp per label edge, fp16 gathers, fp32 dot over 128 dims
// ---------------------------------------------------------------------------
__global__ void k_score(float* __restrict__ out, int L) {
    int gw = (blockIdx.x * blockDim.x + threadIdx.x) >> 5;
    int lane = threadIdx.x & 31;
    if (gw >= L) return;
    int u = g_lidx[gw];
    int v = g_lidx[L + gw];
    uint2 ru = g_x2[(size_t)u * 32 + lane];
    uint2 rv = g_x2[(size_t)v * 32 + lane];
    float2 u0 = __half22float2(*(__half2*)&ru.x);
    float2 u1 = __half22float2(*(__half2*)&ru.y);
    float2 v0 = __half22float2(*(__half2*)&rv.x);
    float2 v1 = __half22float2(*(__half2*)&rv.y);
    float p = u0.x * v0.x + u0.y * v0.y + u1.x * v1.x + u1.y * v1.y;
#pragma unroll
    for (int off = 16; off > 0; off >>= 1)
        p += __shfl_xor_sync(0xffffffffu, p, off);
    if (lane == 0) out[gw] = p;
}

// ---------------------------------------------------------------------------
extern "C" void kernel_launch(void* const* d_in, const int* in_sizes, int n_in,
                              void* d_out, int out_size) {
    const float* X   = (const float*)d_in[0];
    const void* eidx = d_in[1];
    const void* lidx = d_in[2];
    const float* W1  = (const float*)d_in[3];
    const float* b1  = (const float*)d_in[4];
    const float* W2  = (const float*)d_in[5];
    const float* b2  = (const float*)d_in[6];

    int N = in_sizes[0] / 128;
    int E = in_sizes[1] / 2;
    int L = in_sizes[2] / 2;
    int nb1 = (N + 511) / 512;
    int gemmBlocks = (N + 127) / 128;
    int cvtBlocks = (2 * E + 2 * L + 255) / 256;

    static bool attrDone = false;
    if (!attrDone) {
        cudaFuncSetAttribute(k_gemm, cudaFuncAttributeMaxDynamicSharedMemorySize,
                             GEMM_SMEM);
        attrDone = true;
    }

    // Serial pipeline; GEMM1 kept in the ncu-profiled 4th slot.
    k_init<<<(N + 255) / 256, 256>>>((const unsigned*)eidx, N);       // 1
    k_cvt<<<cvtBlocks, 256>>>(eidx, lidx, E, L, N);                   // 2
    k_wcvt<<<32, 256>>>(W1, W2);                                      // 3
    k_gemm<<<gemmBlocks, 256, GEMM_SMEM>>>(X, 0, N, 0);               // 4 <- ncu
    k_scan1<<<nb1, 512>>>(N, nb1);                                    // 5
    k_fill<<<(E + 255) / 256, 256>>>(E);                              // 6
    k_agg<<<(N + 7) / 8, 256>>>(b1, N, 1);                            // 7
    k_gemm<<<gemmBlocks, 256, GEMM_SMEM>>>(X, 1, N, 1);               // 8
    k_agg<<<(N + 7) / 8, 256>>>(b2, N, 0);                            // 9
    k_score<<<(L + 7) / 8, 256>>>((float*)d_out, L);                  // 10
}

// round 14
// speedup vs baseline: 1.0616x; 1.0616x over previous
#include <cuda_runtime.h>
#include <cuda_fp16.h>
#include <cstdint>

#define NMAX 100000
#define EMAX 1000000
#define LMAX 200000

// ---------------------------------------------------------------------------
// Static device scratch (allocation-free)
// ---------------------------------------------------------------------------
__device__ int     g_deg[NMAX];
__device__ float   g_dinv[NMAX];
__device__ int     g_off[NMAX];              // block-local exclusive scan
__device__ int     g_cur[NMAX];              // fill cursors
__device__ int     g_bsum[256];              // scan block sums (exclusive)
__device__ int     g_ticket;                 // scan last-block ticket
__device__ int     g_csr[EMAX];              // CSR: src node per slot
__device__ uint4   g_h[(size_t)NMAX * 16];   // h = x@W, fp16 (256 B/row)
__device__ uint2   g_x2[(size_t)NMAX * 32];  // layer output, fp16 (both layers)
__device__ __half  g_wh[2 * 128 * 128];      // W1,W2 pre-converted to fp16
__device__ int     g_eidx[2 * EMAX];
__device__ int     g_lidx[2 * LMAX];
__device__ int     g_is64;

// ---------------------------------------------------------------------------
// PTX helpers
// ---------------------------------------------------------------------------
__device__ __forceinline__ uint32_t smem_u32(const void* p) {
    uint32_t a;
    asm("{ .reg .u64 t; cvta.to.shared.u64 t, %1; cvt.u32.u64 %0, t; }"
        : "=r"(a) : "l"(p));
    return a;
}
__device__ __forceinline__ void cp16(uint32_t dst, const void* src) {
    asm volatile("cp.async.cg.shared.global [%0], [%1], 16;"
                 :: "r"(dst), "l"(src) : "memory");
}
__device__ __forceinline__ void cp16z(uint32_t dst, const void* src, int sz) {
    asm volatile("cp.async.cg.shared.global [%0], [%1], 16, %2;"
                 :: "r"(dst), "l"(src), "r"(sz) : "memory");
}
#define CP_COMMIT() asm volatile("cp.async.commit_group;" ::: "memory")
#define CP_WAIT0()  asm volatile("cp.async.wait_group 0;" ::: "memory")
#define LDSM_X4(r0, r1, r2, r3, addr)                                        \
    asm volatile("ldmatrix.sync.aligned.m8n8.x4.shared.b16 {%0,%1,%2,%3}, [%4];" \
                 : "=r"(r0), "=r"(r1), "=r"(r2), "=r"(r3) : "r"(addr))
#define LDSM_X4T(r0, r1, r2, r3, addr)                                       \
    asm volatile("ldmatrix.sync.aligned.m8n8.x4.trans.shared.b16 {%0,%1,%2,%3}, [%4];" \
                 : "=r"(r0), "=r"(r1), "=r"(r2), "=r"(r3) : "r"(addr))
#define MMA_16816(c0, c1, c2, c3, a0, a1, a2, a3, b0, b1)                    \
    asm volatile("mma.sync.aligned.m16n8k16.row.col.f32.f16.f16.f32 "        \
                 "{%0,%1,%2,%3}, {%4,%5,%6,%7}, {%8,%9}, {%0,%1,%2,%3};"     \
                 : "+f"(c0), "+f"(c1), "+f"(c2), "+f"(c3)                    \
                 : "r"(a0), "r"(a1), "r"(a2), "r"(a3), "r"(b0), "r"(b1))

// ---------------------------------------------------------------------------
// init: dtype sniff + zero deg/cur + reset ticket + W1,W2 -> fp16
// ---------------------------------------------------------------------------
__global__ void k_init(const unsigned* __restrict__ w, int n,
                       const float* __restrict__ W1,
                       const float* __restrict__ W2) {
    int i = blockIdx.x * blockDim.x + threadIdx.x;
    if (i == 0) {
        int is64 = 1;
        for (int j = 0; j < 32; j++)
            if (w[2 * j + 1] != 0u) { is64 = 0; break; }
        g_is64 = is64;
        g_ticket = 0;
    }
    if (i < n) { g_deg[i] = 0; g_cur[i] = 0; }
    if (i < 8192) {   // 8192 float4 slots across W1+W2
        const float* W = (i < 4096) ? W1 : W2;
        int q = (i < 4096) ? i : i - 4096;
        float4 w4 = *(const float4*)(W + q * 4);
        __half2 p0 = __floats2half2_rn(w4.x, w4.y);
        __half2 p1 = __floats2half2_rn(w4.z, w4.w);
        uint2 pk = { *(uint32_t*)&p0, *(uint32_t*)&p1 };
        *(uint2*)&g_wh[(size_t)i * 4] = pk;
    }
}

// merged edge + label decode (one index space); edges also histogram degrees
__global__ void k_cvt(const void* __restrict__ eraw, const void* __restrict__ lraw,
                      int E, int L, int n) {
    int i = blockIdx.x * blockDim.x + threadIdx.x;
    int twoE = 2 * E;
    int is64 = g_is64;
    if (i < twoE) {
        long long v = is64 ? ((const long long*)eraw)[i]
                           : (long long)((const int*)eraw)[i];
        int x = (int)v;
        x = x < 0 ? 0 : (x >= n ? n - 1 : x);
        g_eidx[i] = x;
        if (i >= E) atomicAdd(&g_deg[x], 1);
    } else if (i < twoE + 2 * L) {
        int j = i - twoE;
        long long v = is64 ? ((const long long*)lraw)[j]
                           : (long long)((const int*)lraw)[j];
        int x = (int)v;
        x = x < 0 ? 0 : (x >= n ? n - 1 : x);
        g_lidx[j] = x;
    }
}

// ---------------------------------------------------------------------------
// Tensor-core GEMM (legacy HMMA path):
// g_h[row] = fp16( X[row] @ W );  fp16 inputs, fp32 accumulate.
// use_internal=0: A = Xext (fp32, converted);  =1: A = g_x2 (fp16, cp.async).
// W from g_wh (fp16, cp.async).
// 256 threads = 8 warps (4M x 2N); warp tile 32M x 64N; K=128 in 8 k16 steps.
// ---------------------------------------------------------------------------
#define HP 136
#define GEMM_SMEM (2 * 128 * HP * 2)   // A + W fp16: 69632 B

__global__ void __launch_bounds__(256, 2)
k_gemm(const float* __restrict__ Xext, int widx, int n, int use_internal) {
    extern __shared__ __half hsm[];
    __half* Asm = hsm;             // [128][HP]
    __half* Wsm = hsm + 128 * HP;  // [128][HP]

    int tid = threadIdx.x;
    int lane = tid & 31;
    int wid = tid >> 5;
    int warpM = wid & 3;
    int warpN = wid >> 2;
    int rowBase = blockIdx.x * 128;

    uint32_t sbA = smem_u32(Asm);
    uint32_t sbW = smem_u32(Wsm);
    const __half* Wh = g_wh + (size_t)widx * 16384;

    // ---- W: fp16 copy via cp.async ----
#pragma unroll
    for (int i = 0; i < 8; i++) {
        int idx = tid + i * 256;          // 0..2047 16B chunks
        int r = idx >> 4;
        int q = idx & 15;
        cp16(sbW + (uint32_t)(r * HP + q * 8) * 2, Wh + r * 128 + q * 8);
    }
    // ---- A: fp32-convert (LDG+cvt) or fp16 cp.async ----
    if (!use_internal) {
#pragma unroll
        for (int i = 0; i < 16; i++) {
            int idx = tid + i * 256;
            int r = idx >> 5;
            int q = idx & 31;
            int row = rowBase + r;
            float4 a4 = make_float4(0.f, 0.f, 0.f, 0.f);
            if (row < n) a4 = *(const float4*)(Xext + (size_t)row * 128 + q * 4);
            __half2 q0 = __floats2half2_rn(a4.x, a4.y);
            __half2 q1 = __floats2half2_rn(a4.z, a4.w);
            uint2 ak = { *(uint32_t*)&q0, *(uint32_t*)&q1 };
            *(uint2*)&Asm[r * HP + q * 4] = ak;
        }
    } else {
        const __half* Xh = (const __half*)g_x2;   // 128 halves per row
#pragma unroll
        for (int i = 0; i < 8; i++) {
            int idx = tid + i * 256;      // 0..2047 16B chunks
            int r = idx >> 4;
            int q = idx & 15;
            int row = rowBase + r;
            int sz = (row < n) ? 16 : 0;
            cp16z(sbA + (uint32_t)(r * HP + q * 8) * 2,
                  Xh + (size_t)row * 128 + q * 8, sz);
        }
    }
    CP_COMMIT();
    CP_WAIT0();
    __syncthreads();

    float acc[2][8][4];
#pragma unroll
    for (int mt = 0; mt < 2; mt++)
#pragma unroll
        for (int nt = 0; nt < 8; nt++)
#pragma unroll
            for (int r = 0; r < 4; r++) acc[mt][nt][r] = 0.f;

    int aRowL = warpM * 32 + (lane & 15);
    int aColL = 8 * (lane >> 4);
    int bRowL = (lane & 7) + 8 * ((lane >> 3) & 1);
    int bColL = warpN * 64 + 8 * (lane >> 4);

#pragma unroll
    for (int ks = 0; ks < 8; ks++) {
        int kb = ks * 16;
        uint32_t a[2][4];
#pragma unroll
        for (int mt = 0; mt < 2; mt++) {
            uint32_t addr = sbA + (uint32_t)((aRowL + mt * 16) * HP + kb + aColL) * 2;
            LDSM_X4(a[mt][0], a[mt][1], a[mt][2], a[mt][3], addr);
        }
        uint32_t b[8][2];
#pragma unroll
        for (int nt2 = 0; nt2 < 4; nt2++) {
            uint32_t addr = sbW + (uint32_t)((kb + bRowL) * HP + bColL + nt2 * 16) * 2;
            uint32_t r0, r1, r2, r3;
            LDSM_X4T(r0, r1, r2, r3, addr);
            b[nt2 * 2 + 0][0] = r0; b[nt2 * 2 + 0][1] = r1;
            b[nt2 * 2 + 1][0] = r2; b[nt2 * 2 + 1][1] = r3;
        }
#pragma unroll
        for (int mt = 0; mt < 2; mt++)
#pragma unroll
            for (int nt = 0; nt < 8; nt++)
                MMA_16816(acc[mt][nt][0], acc[mt][nt][1],
                          acc[mt][nt][2], acc[mt][nt][3],
                          a[mt][0], a[mt][1], a[mt][2], a[mt][3],
                          b[nt][0], b[nt][1]);
    }

    uint32_t* hOut = (uint32_t*)g_h;   // 64 half2 per row
#pragma unroll
    for (int mt = 0; mt < 2; mt++) {
        int r0 = rowBase + warpM * 32 + mt * 16 + (lane >> 2);
#pragma unroll
        for (int nt = 0; nt < 8; nt++) {
            int colIdx = warpN * 32 + nt * 4 + (lane & 3);
            if (r0 < n) {
                __half2 h = __floats2half2_rn(acc[mt][nt][0], acc[mt][nt][1]);
                hOut[(size_t)r0 * 64 + colIdx] = *(uint32_t*)&h;
            }
            if (r0 + 8 < n) {
                __half2 h = __floats2half2_rn(acc[mt][nt][2], acc[mt][nt][3]);
                hOut[(size_t)(r0 + 8) * 64 + colIdx] = *(uint32_t*)&h;
            }
        }
    }
}

// ---------------------------------------------------------------------------
// scan: block-local exclusive + dinv; last block scans the block sums
// ---------------------------------------------------------------------------
__global__ void k_scan1(int n, int nb) {
    __shared__ int s[512];
    __shared__ int isLast;
    int t = threadIdx.x;
    int i = blockIdx.x * 512 + t;
    int v = (i < n) ? g_deg[i] : 0;
    if (i < n) g_dinv[i] = rsqrtf((float)v + 1.0f);
    s[t] = v;
    __syncthreads();
    for (int off = 1; off < 512; off <<= 1) {
        int add = (t >= off) ? s[t - off] : 0;
        __syncthreads();
        s[t] += add;
        __syncthreads();
    }
    if (i < n) g_off[i] = s[t] - v;
    if (t == 511) g_bsum[blockIdx.x] = s[511];

    __threadfence();
    if (t == 0) isLast = (atomicAdd(&g_ticket, 1) == gridDim.x - 1);
    __syncthreads();
    if (isLast) {
        __threadfence();
        int v2 = (t < nb) ? g_bsum[t] : 0;
        s[t] = (t < 256) ? v2 : 0;
        __syncthreads();
        for (int off = 1; off < 256; off <<= 1) {
            int add = (t < 256 && t >= off) ? s[t - off] : 0;
            __syncthreads();
            if (t < 256) s[t] += add;
            __syncthreads();
        }
        if (t < nb) g_bsum[t] = s[t] - v2;
    }
}

__global__ void k_fill(int E) {
    int i = blockIdx.x * blockDim.x + threadIdx.x;
    if (i >= E) return;
    int s = g_eidx[i];
    int d = g_eidx[E + i];
    int pos = g_off[d] + g_bsum[d >> 9] + atomicAdd(&g_cur[d], 1);
    g_csr[pos] = s;
}

// ---------------------------------------------------------------------------
// CSR pull aggregation + fused finalize (fp16 h gathers, fp32 accumulate):
// x2[d] = fp16( act( dinv[d]*(dinv[d]*h[d] + sum_s dinv[s]*h[s]) + b ) )
// ---------------------------------------------------------------------------
__device__ __forceinline__ void h_load4(int row, int lane, float4& f) {
    uint2 raw = ((const uint2*)g_h)[(size_t)row * 32 + lane];
    __half2 p0 = *(__half2*)&raw.x;
    __half2 p1 = *(__half2*)&raw.y;
    float2 a = __half22float2(p0);
    float2 b = __half22float2(p1);
    f.x = a.x; f.y = a.y; f.z = b.x; f.w = b.y;
}

__global__ void k_agg(const float* __restrict__ bias, int n, int do_relu) {
    int gw = (blockIdx.x * blockDim.x + threadIdx.x) >> 5;
    int lane = threadIdx.x & 31;
    if (gw >= n) return;
    int d = gw;

    float wd = g_dinv[d];
    float4 hd; h_load4(d, lane, hd);
    float4 acc = make_float4(wd * hd.x, wd * hd.y, wd * hd.z, wd * hd.w);

    int o = g_off[d] + g_bsum[d >> 9];
    int c = g_deg[d];

    int j = 0;
    for (; j + 4 <= c; j += 4) {
        int s0 = g_csr[o + j + 0];
        int s1 = g_csr[o + j + 1];
        int s2 = g_csr[o + j + 2];
        int s3 = g_csr[o + j + 3];
        float w0 = g_dinv[s0], w1 = g_dinv[s1], w2 = g_dinv[s2], w3 = g_dinv[s3];
        float4 v0, v1, v2, v3;
        h_load4(s0, lane, v0);
        h_load4(s1, lane, v1);
        h_load4(s2, lane, v2);
        h_load4(s3, lane, v3);
        acc.x = fmaf(w0, v0.x, fmaf(w1, v1.x, fmaf(w2, v2.x, fmaf(w3, v3.x, acc.x))));
        acc.y = fmaf(w0, v0.y, fmaf(w1, v1.y, fmaf(w2, v2.y, fmaf(w3, v3.y, acc.y))));
        acc.z = fmaf(w0, v0.z, fmaf(w1, v1.z, fmaf(w2, v2.z, fmaf(w3, v3.z, acc.z))));
        acc.w = fmaf(w0, v0.w, fmaf(w1, v1.w, fmaf(w2, v2.w, fmaf(w3, v3.w, acc.w))));
    }
    for (; j < c; j++) {
        int s = g_csr[o + j];
        float ws = g_dinv[s];
        float4 v; h_load4(s, lane, v);
        acc.x = fmaf(ws, v.x, acc.x);
        acc.y = fmaf(ws, v.y, acc.y);
        acc.z = fmaf(ws, v.z, acc.z);
        acc.w = fmaf(ws, v.w, acc.w);
    }

    float4 bv = ((const float4*)bias)[lane];
    float4 r = make_float4(fmaf(wd, acc.x, bv.x), fmaf(wd, acc.y, bv.y),
                           fmaf(wd, acc.z, bv.z), fmaf(wd, acc.w, bv.w));
    if (do_relu) {
        r.x = fmaxf(r.x, 0.f); r.y = fmaxf(r.y, 0.f);
        r.z = fmaxf(r.z, 0.f); r.w = fmaxf(r.w, 0.f);
    }
    __half2 h0 = __floats2half2_rn(r.x, r.y);
    __half2 h1 = __floats2half2_rn(r.z, r.w);
    uint2 o2;
    o2.x = *(uint32_t*)&h0;
    o2.y = *(uint32_t*)&h1;
    g_x2[(size_t)d * 32 + lane] = o2;
}

// ---------------------------------------------------------------------------
// edge scoring: one warp per label edge, fp16 gathers, fp32 dot over 128 dims
// ---------------------------------------------------------------------------
__global__ void k_score(float* __restrict__ out, int L) {
    int gw = (blockIdx.x * blockDim.x + threadIdx.x) >> 5;
    int lane = threadIdx.x & 31;
    if (gw >= L) return;
    int u = g_lidx[gw];
    int v = g_lidx[L + gw];
    uint2 ru = g_x2[(size_t)u * 32 + lane];
    uint2 rv = g_x2[(size_t)v * 32 + lane];
    float2 u0 = __half22float2(*(__half2*)&ru.x);
    float2 u1 = __half22float2(*(__half2*)&ru.y);
    float2 v0 = __half22float2(*(__half2*)&rv.x);
    float2 v1 = __half22float2(*(__half2*)&rv.y);
    float p = u0.x * v0.x + u0.y * v0.y + u1.x * v1.x + u1.y * v1.y;
#pragma unroll
    for (int off = 16; off > 0; off >>= 1)
        p += __shfl_xor_sync(0xffffffffu, p, off);
    if (lane == 0) out[gw] = p;
}

// ---------------------------------------------------------------------------
extern "C" void kernel_launch(void* const* d_in, const int* in_sizes, int n_in,
                              void* d_out, int out_size) {
    const float* X   = (const float*)d_in[0];
    const void* eidx = d_in[1];
    const void* lidx = d_in[2];
    const float* W1  = (const float*)d_in[3];
    const float* b1  = (const float*)d_in[4];
    const float* W2  = (const float*)d_in[5];
    const float* b2  = (const float*)d_in[6];

    int N = in_sizes[0] / 128;
    int E = in_sizes[1] / 2;
    int L = in_sizes[2] / 2;
    int nb1 = (N + 511) / 512;
    int gemmBlocks = (N + 127) / 128;
    int cvtBlocks = (2 * E + 2 * L + 255) / 256;

    static cudaStream_t s2 = nullptr;
    static cudaEvent_t evFork = nullptr, evJoin = nullptr;
    static bool attrDone = false;
    if (!attrDone) {
        cudaFuncSetAttribute(k_gemm, cudaFuncAttributeMaxDynamicSharedMemorySize,
                             GEMM_SMEM);
        cudaStreamCreateWithFlags(&s2, cudaStreamNonBlocking);
        cudaEventCreateWithFlags(&evFork, cudaEventDisableTiming);
        cudaEventCreateWithFlags(&evJoin, cudaEventDisableTiming);
        attrDone = true;
    }

    // init (zero + sniff + W->fp16), then fork:
    //   s2  : GEMM1 (DRAM-bound, independent of graph structure)
    //   main: CSR build (cvt -> scan -> fill; L2/atomic-bound)
    k_init<<<(N + 255) / 256, 256>>>((const unsigned*)eidx, N, W1, W2);
    cudaEventRecord(evFork, 0);
    cudaStreamWaitEvent(s2, evFork, 0);

    k_gemm<<<gemmBlocks, 256, GEMM_SMEM, s2>>>(X, 0, N, 0);
    cudaEventRecord(evJoin, s2);

    k_cvt<<<cvtBlocks, 256>>>(eidx, lidx, E, L, N);
    k_scan1<<<nb1, 512>>>(N, nb1);
    k_fill<<<(E + 255) / 256, 256>>>(E);

    cudaStreamWaitEvent(0, evJoin, 0);
    k_agg<<<(N + 7) / 8, 256>>>(b1, N, 1);
    k_gemm<<<gemmBlocks, 256, GEMM_SMEM>>>(X, 1, N, 1);
    k_agg<<<(N + 7) / 8, 256>>>(b2, N, 0);
    k_score<<<(L + 7) / 8, 256>>>((float*)d_out, L);
}